// round 12
// baseline (speedup 1.0000x reference)
#include <cuda_runtime.h>
#include <cuda_fp16.h>
#include <cstdint>

#define NUM_HEADS   8
#define HIDDEN_DIM  64
#define N_REAL      30000
#define N_VIRT      2000
#define N_NODES     (N_REAL + N_VIRT)
#define N_EDGES     512000
#define VEC_PER_ROW 16                 // float4 / uint2-of-half4 per node row
#define TB 256
#define N_REP 4                        // h2 replicas to de-contend REDG
#define SCAN_THREADS 1024
#define SCAN_PER     ((N_NODES + SCAN_THREADS - 1) / SCAN_THREADS)  // 32

// fused-kernel block ranges
#define PREP_INDEG_BLOCKS  (N_EDGES / TB)                  // 2000
#define PREP_H0_BLOCKS     (N_NODES * VEC_PER_ROW / TB)    // 2000
#define PREP_VPAIR_BLOCKS  (N_EDGES / TB)                  // 2000
#define PREP_ZERO2_BLOCKS  (N_VIRT * VEC_PER_ROW * N_REP / TB) // 500
#define R2_BLOCKS          2048
#define BCAST_THREADS      (N_VIRT * NUM_HEADS * VEC_PER_ROW)   // 256000

// ---- device scratch (allocation-free) --------------------------------------
struct Zeroed {                         // zeroed with ONE memsetAsync
    int indeg[N_NODES];                 // full in-degree (softmax denominator)
    int ncnt[N_NODES];                  // in-degree restricted to needed dst
    int vcnt;
    unsigned char needed[N_NODES];
};
__device__ Zeroed  g_z;
__device__ __half2 g_h0h[N_NODES * 32];            // f16 node features, 4 MB
__device__ float4  g_h1[N_NODES * VEC_PER_ROW];    // round-1 raw sums (needed rows only)
__device__ float4  g_h2[N_REP][N_VIRT * VEC_PER_ROW]; // round-2 replicas, 2 MB
__device__ int     g_vsrc[N_EDGES];                // virtual-dst edge src ids
__device__ int     g_vdst[N_EDGES];                // matching virtual dst (0..N_VIRT-1)
__device__ int     g_rowptr[N_NODES + 1];          // CSR rowptr (needed-dst edges)
__device__ int     g_cursor[N_NODES];
__device__ int     g_csrc[N_EDGES];                // CSR src ids

__device__ __forceinline__ void red_add_v4(float4* addr, float4 v) {
    asm volatile("red.global.add.v4.f32 [%0], {%1,%2,%3,%4};"
                 :: "l"(addr), "f"(v.x), "f"(v.y), "f"(v.z), "f"(v.w)
                 : "memory");
}
__device__ __forceinline__ float winv_of(int node) {
    float di = (float)g_z.indeg[node];
    return di > 0.f ? __frcp_rn(di) : 0.f;
}

// ---------------------------------------------------------------------------
// K_prep (fused, block-range dispatch):
//   A: full in-degree histogram    B: build f16 h0
//   D: append (src, dst-N_REAL) pairs for virtual-dst edges + mark needed[src]
//   E: zero h2 replicas
__global__ void k_prep(const float4* __restrict__ features,
                       const float4* __restrict__ virtue_emb,
                       const int* __restrict__ cnodes,
                       const int* __restrict__ src,
                       const int* __restrict__ dst) {
    int b = blockIdx.x;
    if (b < PREP_INDEG_BLOCKS) {
        int e = b * TB + threadIdx.x;
        atomicAdd(&g_z.indeg[dst[e]], 1);
        return;
    }
    b -= PREP_INDEG_BLOCKS;
    if (b < PREP_H0_BLOCKS) {
        int t = b * TB + threadIdx.x;
        int v = t >> 4;
        int c = t & 15;
        float4 x;
        if (v < N_REAL) {
            int w = cnodes[v];
            x = features[(size_t)w * VEC_PER_ROW + c];
        } else {
            x = virtue_emb[(size_t)(v - N_REAL) * VEC_PER_ROW + c];
        }
        g_h0h[t * 2]     = __floats2half2_rn(x.x, x.y);
        g_h0h[t * 2 + 1] = __floats2half2_rn(x.z, x.w);
        return;
    }
    b -= PREP_H0_BLOCKS;
    if (b < PREP_VPAIR_BLOCKS) {
        int e = b * TB + threadIdx.x;
        int dd = dst[e];
        if (dd < N_REAL) return;
        int s = src[e];
        int pos = atomicAdd(&g_z.vcnt, 1);
        g_vsrc[pos] = s;
        g_vdst[pos] = dd - N_REAL;
        g_z.needed[s] = 1;               // benign race
        return;
    }
    b -= PREP_VPAIR_BLOCKS;
    {
        int t = b * TB + threadIdx.x;
        ((float4*)g_h2)[t] = make_float4(0.f, 0.f, 0.f, 0.f);
    }
}

// K_count: histogram of in-edges restricted to needed destinations.
// (Must run after k_prep because needed[] is written there.)
__global__ void k_count(const int* __restrict__ dst) {
    int e = blockIdx.x * TB + threadIdx.x;
    int d = dst[e];
    if (g_z.needed[d]) atomicAdd(&g_z.ncnt[d], 1);
}

// K_scan (single block): exclusive scan of ncnt -> rowptr, cursor.
__global__ void k_scan() {
    __shared__ int part[SCAN_THREADS];
    int t = threadIdx.x;
    int base = t * SCAN_PER;

    int s = 0;
#pragma unroll
    for (int i = 0; i < SCAN_PER; i++) {
        int idx = base + i;
        if (idx < N_NODES) s += g_z.ncnt[idx];
    }
    part[t] = s;
    __syncthreads();
    for (int off = 1; off < SCAN_THREADS; off <<= 1) {
        int v = (t >= off) ? part[t - off] : 0;
        __syncthreads();
        part[t] += v;
        __syncthreads();
    }
    int run = (t == 0) ? 0 : part[t - 1];
#pragma unroll
    for (int i = 0; i < SCAN_PER; i++) {
        int idx = base + i;
        if (idx < N_NODES) {
            g_rowptr[idx] = run;
            g_cursor[idx] = run;
            run += g_z.ncnt[idx];
        }
    }
    if (t == SCAN_THREADS - 1) g_rowptr[N_NODES] = run;
}

// K_cscatter: place src ids of needed-dst edges into CSR slots.
__global__ void k_cscatter(const int* __restrict__ src,
                           const int* __restrict__ dst) {
    int e = blockIdx.x * TB + threadIdx.x;
    int d = dst[e];
    if (!g_z.needed[d]) return;
    int pos = atomicAdd(&g_cursor[d], 1);
    g_csrc[pos] = src[e];
}

// K_round1g: gather form. 16 lanes per needed node; 4-way batched neighbor
// loads for MLP; one coalesced 16B store per lane. No atomics, no h1 zeroing.
__global__ void k_round1g() {
    int t = blockIdx.x * TB + threadIdx.x;
    int v = t >> 4;
    int c = t & 15;
    if (!g_z.needed[v]) return;
    int beg = g_rowptr[v];
    int end = g_rowptr[v + 1];

    const uint2* h0 = reinterpret_cast<const uint2*>(g_h0h);
    float4 acc = make_float4(0.f, 0.f, 0.f, 0.f);

    int i = beg;
    for (; i + 4 <= end; i += 4) {
        int s0 = g_csrc[i + 0];
        int s1 = g_csrc[i + 1];
        int s2 = g_csrc[i + 2];
        int s3 = g_csrc[i + 3];
        uint2 q0 = h0[s0 * VEC_PER_ROW + c];
        uint2 q1 = h0[s1 * VEC_PER_ROW + c];
        uint2 q2 = h0[s2 * VEC_PER_ROW + c];
        uint2 q3 = h0[s3 * VEC_PER_ROW + c];
#pragma unroll
        for (int k = 0; k < 4; k++) {
            uint2 q = (k == 0) ? q0 : (k == 1) ? q1 : (k == 2) ? q2 : q3;
            float2 fa = __half22float2(*reinterpret_cast<__half2*>(&q.x));
            float2 fb = __half22float2(*reinterpret_cast<__half2*>(&q.y));
            acc.x += fa.x; acc.y += fa.y; acc.z += fb.x; acc.w += fb.y;
        }
    }
    for (; i < end; i++) {
        int s = g_csrc[i];
        uint2 q = h0[s * VEC_PER_ROW + c];
        float2 fa = __half22float2(*reinterpret_cast<__half2*>(&q.x));
        float2 fb = __half22float2(*reinterpret_cast<__half2*>(&q.y));
        acc.x += fa.x; acc.y += fa.y; acc.z += fb.x; acc.w += fb.y;
    }
    g_h1[v * VEC_PER_ROW + c] = acc;
}

// K_round2e: edge-parallel round 2 over appended (src, vdst) pairs.
// x = h1raw[s] * winv[s]; reduce into one of 4 h2 replicas.
__global__ void k_round2e() {
    int nv = g_z.vcnt;
    int total = nv * VEC_PER_ROW;
    int rep = (threadIdx.x >> 5) & (N_REP - 1);
    for (int t = blockIdx.x * blockDim.x + threadIdx.x; t < total;
         t += gridDim.x * blockDim.x) {
        int e = t >> 4;
        int c = t & 15;
        int s = g_vsrc[e];
        int r = g_vdst[e];
        float w = winv_of(s);
        float4 x = g_h1[s * VEC_PER_ROW + c];
        x.x *= w; x.y *= w; x.z *= w; x.w *= w;
        red_add_v4(&g_h2[rep][r * VEC_PER_ROW + c], x);
    }
}

// K_bcast: one thread per OUTPUT float4; sums the 4 replicas, scales by
// winv[dst], one coalesced 16B store each.
__global__ void k_bcast(const int* __restrict__ vm_idx,
                        float4* __restrict__ out) {
    int t = blockIdx.x * blockDim.x + threadIdx.x;
    if (t >= BCAST_THREADS) return;
    int c = t & 15;
    int u = t >> 7;
    int r = vm_idx[u] - N_REAL;
    int idx = r * VEC_PER_ROW + c;
    float4 acc = make_float4(0.f, 0.f, 0.f, 0.f);
#pragma unroll
    for (int k = 0; k < N_REP; k++) {
        float4 x = g_h2[k][idx];
        acc.x += x.x; acc.y += x.y; acc.z += x.z; acc.w += x.w;
    }
    float w = winv_of(r + N_REAL);
    acc.x *= w; acc.y *= w; acc.z *= w; acc.w *= w;
    out[t] = acc;
}

// ---------------------------------------------------------------------------
extern "C" void kernel_launch(void* const* d_in, const int* in_sizes, int n_in,
                              void* d_out, int out_size) {
    const float4* features   = (const float4*)d_in[0];  // [100000,64] f32
    const float4* virtue_emb = (const float4*)d_in[1];  // [2000,64]   f32
    const int*    cnodes     = (const int*)d_in[2];     // [30000] i32
    const int*    src        = (const int*)d_in[3];     // [512000] i32
    const int*    dst        = (const int*)d_in[4];     // [512000] i32
    const int*    vm_idx     = (const int*)d_in[5];     // [2000] i32
    float4*       out        = (float4*)d_out;          // [2000,8,64] f32

    void* p_z;
    cudaGetSymbolAddress(&p_z, g_z);
    cudaMemsetAsync(p_z, 0, sizeof(Zeroed), 0);

    k_prep    <<<PREP_INDEG_BLOCKS + PREP_H0_BLOCKS + PREP_VPAIR_BLOCKS +
                 PREP_ZERO2_BLOCKS, TB>>>(features, virtue_emb, cnodes, src, dst);
    k_count   <<<N_EDGES / TB, TB>>>(dst);
    k_scan    <<<1, SCAN_THREADS>>>();
    k_cscatter<<<N_EDGES / TB, TB>>>(src, dst);
    k_round1g <<<N_NODES * VEC_PER_ROW / TB, TB>>>();
    k_round2e <<<R2_BLOCKS, TB>>>();
    k_bcast   <<<(BCAST_THREADS + TB - 1) / TB, TB>>>(vm_idx, out);
}

// round 13
// speedup vs baseline: 2.7276x; 2.7276x over previous
#include <cuda_runtime.h>
#include <cuda_fp16.h>
#include <cstdint>

#define NUM_HEADS   8
#define HIDDEN_DIM  64
#define N_REAL      30000
#define N_VIRT      2000
#define N_NODES     (N_REAL + N_VIRT)
#define N_EDGES     512000
#define VEC_PER_ROW 16                 // float4 (or uint2-of-half4) per node row
#define TB 256
#define N_REP 4                        // h2 replicas to de-contend REDG

// fused-kernel block ranges
#define PREP_INDEG_BLOCKS  (N_EDGES / TB)                  // 2000
#define PREP_H0_BLOCKS     (N_NODES * VEC_PER_ROW / TB)    // 2000
#define PREP_ZERO1_BLOCKS  (N_NODES * VEC_PER_ROW / TB)    // 2000
#define PREP_VPAIR_BLOCKS  (N_EDGES / TB)                  // 2000
#define PREP_ZERO2_BLOCKS  (N_VIRT * VEC_PER_ROW * N_REP / TB) // 500
#define E_PER 8
#define R1_BLOCKS          (N_EDGES / E_PER * VEC_PER_ROW / TB) // 4000
#define R2_BLOCKS          2048

// ---- device scratch (allocation-free) --------------------------------------
struct Zeroed {                         // zeroed with ONE memsetAsync
    int indeg[N_NODES];
    int vcnt;
    unsigned char needed[N_NODES];
};
__device__ Zeroed  g_z;
__device__ __half2 g_h0h[N_NODES * 32];            // f16 node features, 4 MB
__device__ float4  g_h1[N_NODES * VEC_PER_ROW];    // round-1 raw sums, 8 MB
__device__ float4  g_h2[N_REP][N_VIRT * VEC_PER_ROW]; // round-2 replicas, 2 MB
__device__ int     g_vsrc[N_EDGES];                // virtual-dst edge src ids
__device__ int     g_vdst[N_EDGES];                // matching virtual dst (0..N_VIRT-1)

__device__ __forceinline__ void red_add_v4(float4* addr, float4 v) {
    asm volatile("red.global.add.v4.f32 [%0], {%1,%2,%3,%4};"
                 :: "l"(addr), "f"(v.x), "f"(v.y), "f"(v.z), "f"(v.w)
                 : "memory");
}
__device__ __forceinline__ float winv_of(int node) {
    float di = (float)g_z.indeg[node];
    return di > 0.f ? __frcp_rn(di) : 0.f;
}

// ---------------------------------------------------------------------------
// K_prep (fused, block-range dispatch):
//   A: in-degree histogram     B: build f16 h0     C: zero h1
//   D: append (src, dst-N_REAL) pairs for virtual-dst edges + mark needed[src]
//   E: zero h2 replicas
__global__ void k_prep(const float4* __restrict__ features,
                       const float4* __restrict__ virtue_emb,
                       const int* __restrict__ cnodes,
                       const int* __restrict__ src,
                       const int* __restrict__ dst) {
    int b = blockIdx.x;
    if (b < PREP_INDEG_BLOCKS) {
        int e = b * TB + threadIdx.x;
        atomicAdd(&g_z.indeg[dst[e]], 1);
        return;
    }
    b -= PREP_INDEG_BLOCKS;
    if (b < PREP_H0_BLOCKS) {
        int t = b * TB + threadIdx.x;
        int v = t >> 4;
        int c = t & 15;
        float4 x;
        if (v < N_REAL) {
            int w = cnodes[v];
            x = features[(size_t)w * VEC_PER_ROW + c];
        } else {
            x = virtue_emb[(size_t)(v - N_REAL) * VEC_PER_ROW + c];
        }
        g_h0h[t * 2]     = __floats2half2_rn(x.x, x.y);
        g_h0h[t * 2 + 1] = __floats2half2_rn(x.z, x.w);
        return;
    }
    b -= PREP_H0_BLOCKS;
    if (b < PREP_ZERO1_BLOCKS) {
        int t = b * TB + threadIdx.x;
        g_h1[t] = make_float4(0.f, 0.f, 0.f, 0.f);
        return;
    }
    b -= PREP_ZERO1_BLOCKS;
    if (b < PREP_VPAIR_BLOCKS) {
        int e = b * TB + threadIdx.x;
        int dd = dst[e];
        if (dd < N_REAL) return;
        int s = src[e];
        int pos = atomicAdd(&g_z.vcnt, 1);
        g_vsrc[pos] = s;
        g_vdst[pos] = dd - N_REAL;
        g_z.needed[s] = 1;               // benign race
        return;
    }
    b -= PREP_VPAIR_BLOCKS;
    {
        int t = b * TB + threadIdx.x;
        ((float4*)g_h2)[t] = make_float4(0.f, 0.f, 0.f, 0.f);
    }
}

// K_round1: h1raw[d] += h0f16[s] for edges whose dst is needed.
// 16 lanes per edge, 8 edges per thread, loads batched for MLP.
__global__ void k_round1(const int* __restrict__ src,
                         const int* __restrict__ dst) {
    int t = blockIdx.x * TB + threadIdx.x;
    int c  = t & 15;
    int e0 = (t >> 4) * E_PER;

    int s[E_PER], d[E_PER];
#pragma unroll
    for (int j = 0; j < E_PER; j++) { s[j] = src[e0 + j]; d[j] = dst[e0 + j]; }
    unsigned char f[E_PER];
#pragma unroll
    for (int j = 0; j < E_PER; j++) f[j] = g_z.needed[d[j]];

    const uint2* h0 = reinterpret_cast<const uint2*>(g_h0h);
    uint2 q[E_PER];
#pragma unroll
    for (int j = 0; j < E_PER; j++)
        if (f[j]) q[j] = h0[s[j] * VEC_PER_ROW + c];
#pragma unroll
    for (int j = 0; j < E_PER; j++) {
        if (!f[j]) continue;
        __half2 a = *reinterpret_cast<__half2*>(&q[j].x);
        __half2 bb = *reinterpret_cast<__half2*>(&q[j].y);
        float2 fa = __half22float2(a);
        float2 fb = __half22float2(bb);
        red_add_v4(&g_h1[d[j] * VEC_PER_ROW + c],
                   make_float4(fa.x, fa.y, fb.x, fb.y));
    }
}

// K_round2e: edge-parallel round 2 over appended (src, vdst) pairs.
// x = h1raw[s] * winv[s]; reduce into one of 4 h2 replicas.
__global__ void k_round2e() {
    int nv = g_z.vcnt;
    int total = nv * VEC_PER_ROW;
    int rep = (threadIdx.x >> 5) & (N_REP - 1);
    for (int t = blockIdx.x * blockDim.x + threadIdx.x; t < total;
         t += gridDim.x * blockDim.x) {
        int e = t >> 4;
        int c = t & 15;
        int s = g_vsrc[e];
        int r = g_vdst[e];
        float w = winv_of(s);
        float4 x = g_h1[s * VEC_PER_ROW + c];
        x.x *= w; x.y *= w; x.z *= w; x.w *= w;
        red_add_v4(&g_h2[rep][r * VEC_PER_ROW + c], x);
    }
}

// K_bcast (R8 narrow form — measured faster than the wide variant):
// sums replicas, scales by winv[dst], broadcasts across 8 heads.
__global__ void k_bcast(const int* __restrict__ vm_idx,
                        float4* __restrict__ out) {
    int t = blockIdx.x * blockDim.x + threadIdx.x;
    if (t >= N_VIRT * VEC_PER_ROW) return;
    int u = t >> 4;
    int c = t & 15;
    int r = vm_idx[u] - N_REAL;
    int idx = r * VEC_PER_ROW + c;
    float4 acc = make_float4(0.f, 0.f, 0.f, 0.f);
#pragma unroll
    for (int k = 0; k < N_REP; k++) {
        float4 x = g_h2[k][idx];
        acc.x += x.x; acc.y += x.y; acc.z += x.z; acc.w += x.w;
    }
    float w = winv_of(r + N_REAL);
    acc.x *= w; acc.y *= w; acc.z *= w; acc.w *= w;
#pragma unroll
    for (int h = 0; h < NUM_HEADS; h++) {
        out[((size_t)u * NUM_HEADS + h) * VEC_PER_ROW + c] = acc;
    }
}

// ---------------------------------------------------------------------------
extern "C" void kernel_launch(void* const* d_in, const int* in_sizes, int n_in,
                              void* d_out, int out_size) {
    const float4* features   = (const float4*)d_in[0];  // [100000,64] f32
    const float4* virtue_emb = (const float4*)d_in[1];  // [2000,64]   f32
    const int*    cnodes     = (const int*)d_in[2];     // [30000] i32
    const int*    src        = (const int*)d_in[3];     // [512000] i32
    const int*    dst        = (const int*)d_in[4];     // [512000] i32
    const int*    vm_idx     = (const int*)d_in[5];     // [2000] i32
    float4*       out        = (float4*)d_out;          // [2000,8,64] f32

    void* p_z;
    cudaGetSymbolAddress(&p_z, g_z);
    cudaMemsetAsync(p_z, 0, sizeof(Zeroed), 0);

    k_prep   <<<PREP_INDEG_BLOCKS + PREP_H0_BLOCKS + PREP_ZERO1_BLOCKS +
                PREP_VPAIR_BLOCKS + PREP_ZERO2_BLOCKS, TB>>>(
                 features, virtue_emb, cnodes, src, dst);
    k_round1 <<<R1_BLOCKS, TB>>>(src, dst);
    k_round2e<<<R2_BLOCKS, TB>>>();
    k_bcast  <<<(N_VIRT * VEC_PER_ROW + TB - 1) / TB, TB>>>(vm_idx, out);
}

// round 14
// speedup vs baseline: 2.9845x; 1.0942x over previous
#include <cuda_runtime.h>
#include <cuda_fp16.h>
#include <cstdint>

#define NUM_HEADS   8
#define HIDDEN_DIM  64
#define N_REAL      30000
#define N_VIRT      2000
#define N_NODES     (N_REAL + N_VIRT)
#define N_EDGES     512000
#define VEC_PER_ROW 16                 // float4 (or uint2-of-half4) per node row
#define TB 256
#define N_REP 4                        // h2 replicas to de-contend REDG

// fused-kernel block ranges
#define PREP_INDEG_BLOCKS  (N_EDGES / TB)                  // 2000
#define PREP_H0_BLOCKS     (N_NODES * VEC_PER_ROW / TB)    // 2000
#define PREP_ZERO1_BLOCKS  (N_NODES * VEC_PER_ROW / TB)    // 2000
#define PREP_VPAIR_BLOCKS  (N_EDGES / TB)                  // 2000
#define PREP_ZERO2_BLOCKS  (N_VIRT * VEC_PER_ROW * N_REP / TB) // 500
#define E_PER 4
#define R1_BLOCKS          (N_EDGES / E_PER * VEC_PER_ROW / TB) // 8000
#define R2_BLOCKS          2048
#define R2_WV_BLOCKS       ((N_VIRT + TB - 1) / TB)        // 8
#define BC_OUT_BLOCKS      (N_VIRT * VEC_PER_ROW / TB)     // 125

// ---- device scratch (allocation-free) --------------------------------------
// Invariant: g_z is ZERO on entry to kernel_launch. Established by static
// zero-init at module load, maintained by the zeroing role at the end of
// k_bcast on every call. This removes the per-call cudaMemsetAsync launch.
struct __align__(16) Zeroed {
    int indeg[N_NODES];
    int vcnt;
    unsigned char needed[N_NODES];
};
__device__ Zeroed  g_z;
#define ZERO_CHUNKS  ((sizeof(Zeroed) + 15) / 16)
#define BC_ZERO_BLOCKS ((ZERO_CHUNKS + TB - 1) / TB)       // ~40

__device__ __half2 g_h0h[N_NODES * 32];            // f16 node features, 4 MB
__device__ float4  g_h1[N_NODES * VEC_PER_ROW];    // round-1 raw sums, 8 MB
__device__ float4  g_h2[N_REP][N_VIRT * VEC_PER_ROW]; // round-2 replicas, 2 MB
__device__ int     g_vpack[N_EDGES];               // packed (src | vdst<<16)
__device__ float   g_wv[N_VIRT];                   // winv of virtual nodes

__device__ __forceinline__ void red_add_v4(float4* addr, float4 v) {
    asm volatile("red.global.add.v4.f32 [%0], {%1,%2,%3,%4};"
                 :: "l"(addr), "f"(v.x), "f"(v.y), "f"(v.z), "f"(v.w)
                 : "memory");
}
__device__ __forceinline__ float winv_of(int node) {
    float di = (float)g_z.indeg[node];
    return di > 0.f ? __frcp_rn(di) : 0.f;
}

// ---------------------------------------------------------------------------
// K_prep (fused, block-range dispatch):
//   A: in-degree histogram     B: build f16 h0     C: zero h1
//   D: append packed (src, dst-N_REAL) for virtual-dst edges + mark needed[src]
//   E: zero h2 replicas
__global__ void k_prep(const float4* __restrict__ features,
                       const float4* __restrict__ virtue_emb,
                       const int* __restrict__ cnodes,
                       const int* __restrict__ src,
                       const int* __restrict__ dst) {
    int b = blockIdx.x;
    if (b < PREP_INDEG_BLOCKS) {
        int e = b * TB + threadIdx.x;
        atomicAdd(&g_z.indeg[dst[e]], 1);
        return;
    }
    b -= PREP_INDEG_BLOCKS;
    if (b < PREP_H0_BLOCKS) {
        int t = b * TB + threadIdx.x;
        int v = t >> 4;
        int c = t & 15;
        float4 x;
        if (v < N_REAL) {
            int w = cnodes[v];
            x = features[(size_t)w * VEC_PER_ROW + c];
        } else {
            x = virtue_emb[(size_t)(v - N_REAL) * VEC_PER_ROW + c];
        }
        g_h0h[t * 2]     = __floats2half2_rn(x.x, x.y);
        g_h0h[t * 2 + 1] = __floats2half2_rn(x.z, x.w);
        return;
    }
    b -= PREP_H0_BLOCKS;
    if (b < PREP_ZERO1_BLOCKS) {
        int t = b * TB + threadIdx.x;
        g_h1[t] = make_float4(0.f, 0.f, 0.f, 0.f);
        return;
    }
    b -= PREP_ZERO1_BLOCKS;
    if (b < PREP_VPAIR_BLOCKS) {
        int e = b * TB + threadIdx.x;
        int dd = dst[e];
        if (dd < N_REAL) return;
        int s = src[e];
        int pos = atomicAdd(&g_z.vcnt, 1);
        g_vpack[pos] = s | ((dd - N_REAL) << 16);   // s < 32000 fits 16 bits
        g_z.needed[s] = 1;               // benign race
        return;
    }
    b -= PREP_VPAIR_BLOCKS;
    {
        int t = b * TB + threadIdx.x;
        ((float4*)g_h2)[t] = make_float4(0.f, 0.f, 0.f, 0.f);
    }
}

// K_round1: h1raw[d] += h0f16[s] for edges whose dst is needed.
// 16 lanes per edge, 4 edges per thread, loads batched for MLP.
__global__ void k_round1(const int* __restrict__ src,
                         const int* __restrict__ dst) {
    int t = blockIdx.x * TB + threadIdx.x;
    int c  = t & 15;
    int e0 = (t >> 4) * E_PER;

    int s[E_PER], d[E_PER];
#pragma unroll
    for (int j = 0; j < E_PER; j++) { s[j] = src[e0 + j]; d[j] = dst[e0 + j]; }
    unsigned char f[E_PER];
#pragma unroll
    for (int j = 0; j < E_PER; j++) f[j] = g_z.needed[d[j]];

    const uint2* h0 = reinterpret_cast<const uint2*>(g_h0h);
    uint2 q[E_PER];
#pragma unroll
    for (int j = 0; j < E_PER; j++)
        if (f[j]) q[j] = h0[s[j] * VEC_PER_ROW + c];
#pragma unroll
    for (int j = 0; j < E_PER; j++) {
        if (!f[j]) continue;
        __half2 a = *reinterpret_cast<__half2*>(&q[j].x);
        __half2 bb = *reinterpret_cast<__half2*>(&q[j].y);
        float2 fa = __half22float2(a);
        float2 fb = __half22float2(bb);
        red_add_v4(&g_h1[d[j] * VEC_PER_ROW + c],
                   make_float4(fa.x, fa.y, fb.x, fb.y));
    }
}

// K_round2e: edge-parallel round 2 over packed (src, vdst) pairs, plus a
// small side role computing g_wv for the virtual nodes (last reader of
// indeg before k_bcast's zeroing role).
__global__ void k_round2e() {
    if (blockIdx.x >= R2_BLOCKS) {
        int u = (blockIdx.x - R2_BLOCKS) * TB + threadIdx.x;
        if (u < N_VIRT) g_wv[u] = winv_of(u + N_REAL);
        return;
    }
    int nv = g_z.vcnt;
    int total = nv * VEC_PER_ROW;
    int rep = (threadIdx.x >> 5) & (N_REP - 1);
    for (int t = blockIdx.x * TB + threadIdx.x; t < total;
         t += R2_BLOCKS * TB) {
        int e = t >> 4;
        int c = t & 15;
        int pk = g_vpack[e];
        int s = pk & 0xFFFF;
        int r = pk >> 16;
        float w = winv_of(s);
        float4 x = g_h1[s * VEC_PER_ROW + c];
        x.x *= w; x.y *= w; x.z *= w; x.w *= w;
        red_add_v4(&g_h2[rep][r * VEC_PER_ROW + c], x);
    }
}

// K_bcast: role A sums replicas, scales by g_wv, broadcasts across 8 heads
// (never touches g_z). Role B re-zeroes g_z for the next call, restoring
// the entry invariant (replaces the per-call memset launch).
__global__ void k_bcast(const int* __restrict__ vm_idx,
                        float4* __restrict__ out) {
    int b = blockIdx.x;
    if (b < BC_OUT_BLOCKS) {
        int t = b * TB + threadIdx.x;
        int u = t >> 4;
        int c = t & 15;
        int r = vm_idx[u] - N_REAL;
        int idx = r * VEC_PER_ROW + c;
        float4 acc = make_float4(0.f, 0.f, 0.f, 0.f);
#pragma unroll
        for (int k = 0; k < N_REP; k++) {
            float4 x = g_h2[k][idx];
            acc.x += x.x; acc.y += x.y; acc.z += x.z; acc.w += x.w;
        }
        float w = g_wv[r];
        acc.x *= w; acc.y *= w; acc.z *= w; acc.w *= w;
#pragma unroll
        for (int h = 0; h < NUM_HEADS; h++) {
            out[((size_t)u * NUM_HEADS + h) * VEC_PER_ROW + c] = acc;
        }
        return;
    }
    b -= BC_OUT_BLOCKS;
    {
        unsigned int ch = b * TB + threadIdx.x;
        if (ch < ZERO_CHUNKS) {
            ((float4*)&g_z)[ch] = make_float4(0.f, 0.f, 0.f, 0.f);
        }
    }
}

// ---------------------------------------------------------------------------
extern "C" void kernel_launch(void* const* d_in, const int* in_sizes, int n_in,
                              void* d_out, int out_size) {
    const float4* features   = (const float4*)d_in[0];  // [100000,64] f32
    const float4* virtue_emb = (const float4*)d_in[1];  // [2000,64]   f32
    const int*    cnodes     = (const int*)d_in[2];     // [30000] i32
    const int*    src        = (const int*)d_in[3];     // [512000] i32
    const int*    dst        = (const int*)d_in[4];     // [512000] i32
    const int*    vm_idx     = (const int*)d_in[5];     // [2000] i32
    float4*       out        = (float4*)d_out;          // [2000,8,64] f32

    k_prep   <<<PREP_INDEG_BLOCKS + PREP_H0_BLOCKS + PREP_ZERO1_BLOCKS +
                PREP_VPAIR_BLOCKS + PREP_ZERO2_BLOCKS, TB>>>(
                 features, virtue_emb, cnodes, src, dst);
    k_round1 <<<R1_BLOCKS, TB>>>(src, dst);
    k_round2e<<<R2_BLOCKS + R2_WV_BLOCKS, TB>>>();
    k_bcast  <<<BC_OUT_BLOCKS + BC_ZERO_BLOCKS, TB>>>(vm_idx, out);
}